// round 1
// baseline (speedup 1.0000x reference)
#include <cuda_runtime.h>
#include <cuda_bf16.h>

// SurvLoss: loss = (sum_t max(0, segmax_t(log cumsum exp(outs))) * segcnt_t(E)
//                   - sum(outs*E)) / sum(E)
// N = 16777216, NUM_TIMES = 1024 segments.
//
// 4-kernel deterministic pipeline:
//   K1: per-block sums of exp(outs)            (1024 blocks, 16384 elems each)
//   K2: double-precision exclusive scan of the 1024 block sums + zero-init
//   K3: main pass: within-block inclusive scan, y=log(prefix+incl), clamp 0,
//       smem segment max/count, global combine; also sum(outs*E), sum(E)
//   K4: finalize scalar

#define N_TOTAL   16777216
#define NUM_TIMES 1024
#define NBLK      1024
#define THREADS   256
#define CHUNKS    16                       // 16 * 256 * 4 = 16384 elems / block
#define TILE      (CHUNKS * THREADS * 4)

__device__ float              g_block_agg[NBLK];
__device__ double             g_block_prefix[NBLK];
__device__ int                g_seg_max_bits[NUM_TIMES];   // float bits, all >= 0
__device__ int                g_seg_cnt[NUM_TIMES];
__device__ double             g_s1;
__device__ unsigned long long g_obs;

// ---------------------------------------------------------------- K1
__global__ void __launch_bounds__(THREADS) k1_block_sums(const float* __restrict__ outs) {
    const int b = blockIdx.x, tid = threadIdx.x;
    const float4* o4 = (const float4*)outs;
    const int base = b * (TILE / 4);

    float s = 0.f;
#pragma unroll
    for (int c = 0; c < CHUNKS; c++) {
        float4 v = o4[base + c * THREADS + tid];
        s += __expf(v.x) + __expf(v.y) + __expf(v.z) + __expf(v.w);
    }
#pragma unroll
    for (int o = 16; o; o >>= 1) s += __shfl_xor_sync(0xffffffffu, s, o);

    __shared__ float ws[8];
    if ((tid & 31) == 0) ws[tid >> 5] = s;
    __syncthreads();
    if (tid < 8) {
        float t = ws[tid];
#pragma unroll
        for (int o = 4; o; o >>= 1) t += __shfl_xor_sync(0xffu, t, o);
        if (tid == 0) g_block_agg[b] = t;
    }
}

// ---------------------------------------------------------------- K2
// One block, 1024 threads: exclusive scan (double) of g_block_agg, plus init.
__global__ void __launch_bounds__(1024) k2_scan_init() {
    const int tid = threadIdx.x;
    const int lane = tid & 31, w = tid >> 5;

    g_seg_max_bits[tid] = 0;     // float 0.0f bits
    g_seg_cnt[tid] = 0;
    if (tid == 0) { g_s1 = 0.0; g_obs = 0ull; }

    double v = (double)g_block_agg[tid];
    double x = v;
#pragma unroll
    for (int o = 1; o < 32; o <<= 1) {
        double y = __shfl_up_sync(0xffffffffu, x, o);
        if (lane >= o) x += y;
    }
    __shared__ double wsum[32];
    if (lane == 31) wsum[w] = x;
    __syncthreads();
    if (w == 0) {
        double t = wsum[lane];
#pragma unroll
        for (int o = 1; o < 32; o <<= 1) {
            double y = __shfl_up_sync(0xffffffffu, t, o);
            if (lane >= o) t += y;
        }
        wsum[lane] = t;
    }
    __syncthreads();
    double wexcl = (w == 0) ? 0.0 : wsum[w - 1];
    g_block_prefix[tid] = wexcl + (x - v);   // exclusive prefix for block tid
}

// ---------------------------------------------------------------- K3
__global__ void __launch_bounds__(THREADS) k3_main(const float* __restrict__ outs,
                                                   const int* __restrict__ T_E,
                                                   const int* __restrict__ T_T) {
    __shared__ int   s_max[NUM_TIMES];
    __shared__ int   s_cnt[NUM_TIMES];
    __shared__ float warp_tot[8];
    __shared__ float red_s1[8];
    __shared__ int   red_ob[8];

    const int b = blockIdx.x, tid = threadIdx.x;
    const int lane = tid & 31, w = tid >> 5;

    for (int i = tid; i < NUM_TIMES; i += THREADS) { s_max[i] = 0; s_cnt[i] = 0; }

    double carry = g_block_prefix[b];

    const float4* o4 = (const float4*)outs;
    const int4*   e4 = (const int4*)T_E;
    const int4*   t4 = (const int4*)T_T;
    const int base = b * (TILE / 4);

    float local_s1 = 0.f;
    int   local_ob = 0;

    __syncthreads();

#pragma unroll 1
    for (int c = 0; c < CHUNKS; c++) {
        const int idx = base + c * THREADS + tid;
        float4 v = o4[idx];
        float e0 = __expf(v.x), e1 = __expf(v.y), e2 = __expf(v.z), e3 = __expf(v.w);
        float i0 = e0, i1 = i0 + e1, i2 = i1 + e2, i3 = i2 + e3;
        const float tsum = i3;

        // warp inclusive scan of per-thread totals
        float x = tsum;
#pragma unroll
        for (int o = 1; o < 32; o <<= 1) {
            float y = __shfl_up_sync(0xffffffffu, x, o);
            if (lane >= o) x += y;
        }
        __syncthreads();                 // protect warp_tot from previous iter's readers
        if (lane == 31) warp_tot[w] = x;
        __syncthreads();

        float wexcl = 0.f, tot = 0.f;
#pragma unroll
        for (int k = 0; k < 8; k++) {
            float wt = warp_tot[k];
            tot += wt;
            if (k < w) wexcl += wt;
        }

        const float basef = (float)carry;
        const float excl  = basef + wexcl + (x - tsum);   // exclusive prefix for this thread
        float y0 = fmaxf(__logf(excl + i0), 0.f);
        float y1 = fmaxf(__logf(excl + i1), 0.f);
        float y2 = fmaxf(__logf(excl + i2), 0.f);
        float y3 = fmaxf(__logf(excl + i3), 0.f);

        int4 tt = t4[idx];
        int4 te = e4[idx];
        int s0 = abs(tt.x), s1i = abs(tt.y), s2i = abs(tt.z), s3i = abs(tt.w);

        atomicMax(&s_max[s0],  __float_as_int(y0));
        atomicMax(&s_max[s1i], __float_as_int(y1));
        atomicMax(&s_max[s2i], __float_as_int(y2));
        atomicMax(&s_max[s3i], __float_as_int(y3));

        if (te.x > 0) { atomicAdd(&s_cnt[s0],  1); local_s1 += v.x; local_ob++; }
        if (te.y > 0) { atomicAdd(&s_cnt[s1i], 1); local_s1 += v.y; local_ob++; }
        if (te.z > 0) { atomicAdd(&s_cnt[s2i], 1); local_s1 += v.z; local_ob++; }
        if (te.w > 0) { atomicAdd(&s_cnt[s3i], 1); local_s1 += v.w; local_ob++; }

        carry += (double)tot;
    }

    // block reduce local_s1 / local_ob
#pragma unroll
    for (int o = 16; o; o >>= 1) {
        local_s1 += __shfl_xor_sync(0xffffffffu, local_s1, o);
        local_ob += __shfl_xor_sync(0xffffffffu, local_ob, o);
    }
    if (lane == 0) { red_s1[w] = local_s1; red_ob[w] = local_ob; }
    __syncthreads();
    if (tid < 8) {
        float rs = red_s1[tid];
        int   ro = red_ob[tid];
#pragma unroll
        for (int o = 4; o; o >>= 1) {
            rs += __shfl_xor_sync(0xffu, rs, o);
            ro += __shfl_xor_sync(0xffu, ro, o);
        }
        if (tid == 0) {
            atomicAdd(&g_s1, (double)rs);
            atomicAdd(&g_obs, (unsigned long long)ro);
        }
    }

    // flush segment accumulators to global
    __syncthreads();
    for (int i = tid; i < NUM_TIMES; i += THREADS) {
        int m = s_max[i];
        if (m != 0) atomicMax(&g_seg_max_bits[i], m);
        int cnt = s_cnt[i];
        if (cnt != 0) atomicAdd(&g_seg_cnt[i], cnt);
    }
}

// ---------------------------------------------------------------- K4
__global__ void __launch_bounds__(1024) k4_finalize(float* __restrict__ out) {
    const int tid = threadIdx.x;
    const int lane = tid & 31, w = tid >> 5;

    double p = (double)__int_as_float(g_seg_max_bits[tid]) * (double)g_seg_cnt[tid];
#pragma unroll
    for (int o = 16; o; o >>= 1) p += __shfl_xor_sync(0xffffffffu, p, o);

    __shared__ double ws[32];
    if (lane == 0) ws[w] = p;
    __syncthreads();
    if (w == 0) {
        double t = ws[lane];
#pragma unroll
        for (int o = 16; o; o >>= 1) t += __shfl_xor_sync(0xffffffffu, t, o);
        if (lane == 0) {
            double loss = (t - g_s1) / (double)g_obs;
            out[0] = (float)loss;
        }
    }
}

// ---------------------------------------------------------------- launch
extern "C" void kernel_launch(void* const* d_in, const int* in_sizes, int n_in,
                              void* d_out, int out_size) {
    const float* outs = (const float*)d_in[0];
    const int*   T_E  = (const int*)d_in[1];
    const int*   T_T  = (const int*)d_in[2];
    float* out = (float*)d_out;

    k1_block_sums<<<NBLK, THREADS>>>(outs);
    k2_scan_init<<<1, 1024>>>();
    k3_main<<<NBLK, THREADS>>>(outs, T_E, T_T);
    k4_finalize<<<1, 1024>>>(out);
}

// round 2
// speedup vs baseline: 1.2802x; 1.2802x over previous
#include <cuda_runtime.h>
#include <cuda_bf16.h>

// SurvLoss via monotonicity: log(cumsum(exp)) is increasing, so
// segment_max = value at the LAST occurrence index of each segment.
//
// K1 (single pass over all 192MB):
//   - per-128-elem-span sums of exp(outs)  -> g_wc   (hierarchical cumsum)
//   - per-block sums                        -> g_block_agg
//   - per-segment last index (smem filter + atomicMax, reverse order)
//   - per-segment E-counts, sum(outs*E), sum(E)
// K2: 1-block double exclusive scan of block sums -> g_block_prefix
// K3: warp-per-segment: reconstruct cumsum at the last-occurrence index,
//     y = max(log(total),0), loss = (sum y*cnt - s1)/obs. Resets all state.

#define NUM_TIMES 1024
#define NBLK      1024
#define THREADS   256
#define CHUNKS    16
#define TILE      16384                     // elements per block
#define SPANS     128                       // 128-elem spans per block

__device__ float              g_wc[NBLK * SPANS];     // span sums of exp
__device__ float              g_block_agg[NBLK];
__device__ double             g_block_prefix[NBLK];
__device__ int                g_last[NUM_TIMES];      // 0 = empty, else idx+1
__device__ int                g_cnt[NUM_TIMES];
__device__ double             g_s1;
__device__ unsigned long long g_obs;
__device__ double             g_s2;
__device__ unsigned int       g_done;

// ---------------------------------------------------------------- K1
__global__ void __launch_bounds__(THREADS) k1_main(const float* __restrict__ outs,
                                                   const int* __restrict__ T_E,
                                                   const int* __restrict__ T_T) {
    __shared__ int   s_last[NUM_TIMES];
    __shared__ int   s_cnt[NUM_TIMES];
    __shared__ float wtot[8];
    __shared__ float rs1[8];
    __shared__ int   rob[8];

    const int b = blockIdx.x, tid = threadIdx.x;
    const int lane = tid & 31, w = tid >> 5;

    for (int i = tid; i < NUM_TIMES; i += THREADS) { s_last[i] = 0; s_cnt[i] = 0; }
    __syncthreads();

    const float4* o4 = (const float4*)outs;
    const int4*   e4 = (const int4*)T_E;
    const int4*   t4 = (const int4*)T_T;
    const int base4 = b * (TILE / 4);

    float thr_tot = 0.f;          // per-thread exp sum across all chunks
    float ls1 = 0.f;
    int   lob = 0;

    // Reverse chunk order: high indices processed first so the shared-mem
    // last-occurrence filter kills most atomicMax attempts.
#pragma unroll 4
    for (int c = CHUNKS - 1; c >= 0; --c) {
        const int fi = base4 + c * THREADS + tid;
        float4 v  = o4[fi];
        int4   tt = t4[fi];
        int4   te = e4[fi];

        float s = __expf(v.x) + __expf(v.y) + __expf(v.z) + __expf(v.w);
        thr_tot += s;

        // warp sum of s -> span total (warp w, chunk c covers contiguous 128 elems)
        float x = s;
#pragma unroll
        for (int o = 16; o; o >>= 1) x += __shfl_xor_sync(0xffffffffu, x, o);
        if (lane == 0) g_wc[b * SPANS + c * 8 + w] = x;

        const int gi = fi * 4;    // global element index of v.x

        // last-occurrence (filtered atomicMax on idx+1; benign races only add atomics)
        int sg3 = abs(tt.w); if (s_last[sg3] < gi + 4) atomicMax(&s_last[sg3], gi + 4);
        int sg2 = abs(tt.z); if (s_last[sg2] < gi + 3) atomicMax(&s_last[sg2], gi + 3);
        int sg1 = abs(tt.y); if (s_last[sg1] < gi + 2) atomicMax(&s_last[sg1], gi + 2);
        int sg0 = abs(tt.x); if (s_last[sg0] < gi + 1) atomicMax(&s_last[sg0], gi + 1);

        if (te.x > 0) { atomicAdd(&s_cnt[sg0], 1); ls1 += v.x; lob++; }
        if (te.y > 0) { atomicAdd(&s_cnt[sg1], 1); ls1 += v.y; lob++; }
        if (te.z > 0) { atomicAdd(&s_cnt[sg2], 1); ls1 += v.z; lob++; }
        if (te.w > 0) { atomicAdd(&s_cnt[sg3], 1); ls1 += v.w; lob++; }
    }

    // block reductions: exp total, s1, obs
    float xx = thr_tot;
#pragma unroll
    for (int o = 16; o; o >>= 1) {
        xx  += __shfl_xor_sync(0xffffffffu, xx, o);
        ls1 += __shfl_xor_sync(0xffffffffu, ls1, o);
        lob += __shfl_xor_sync(0xffffffffu, lob, o);
    }
    if (lane == 0) { wtot[w] = xx; rs1[w] = ls1; rob[w] = lob; }
    __syncthreads();
    if (tid == 0) {
        float bt = 0.f, bs = 0.f; int bo = 0;
#pragma unroll
        for (int k = 0; k < 8; k++) { bt += wtot[k]; bs += rs1[k]; bo += rob[k]; }
        g_block_agg[b] = bt;
        atomicAdd(&g_s1, (double)bs);
        atomicAdd(&g_obs, (unsigned long long)bo);
    }

    // flush segment tables
    __syncthreads();
    for (int i = tid; i < NUM_TIMES; i += THREADS) {
        int m = s_last[i];
        if (m) atomicMax(&g_last[i], m);
        int cnt = s_cnt[i];
        if (cnt) atomicAdd(&g_cnt[i], cnt);
    }
}

// ---------------------------------------------------------------- K2
__global__ void __launch_bounds__(1024) k2_scan() {
    const int tid = threadIdx.x;
    const int lane = tid & 31, w = tid >> 5;

    double v = (double)g_block_agg[tid];
    double x = v;
#pragma unroll
    for (int o = 1; o < 32; o <<= 1) {
        double y = __shfl_up_sync(0xffffffffu, x, o);
        if (lane >= o) x += y;
    }
    __shared__ double wsum[32];
    if (lane == 31) wsum[w] = x;
    __syncthreads();
    if (w == 0) {
        double t = wsum[lane];
#pragma unroll
        for (int o = 1; o < 32; o <<= 1) {
            double y = __shfl_up_sync(0xffffffffu, t, o);
            if (lane >= o) t += y;
        }
        wsum[lane] = t;
    }
    __syncthreads();
    double wexcl = (w == 0) ? 0.0 : wsum[w - 1];
    g_block_prefix[tid] = wexcl + (x - v);   // exclusive prefix
}

// ---------------------------------------------------------------- K3
// 128 blocks x 256 threads = 1024 warps; warp g handles segment g.
__global__ void __launch_bounds__(THREADS) k3_finalize(const float* __restrict__ outs,
                                                       float* __restrict__ out) {
    const int tid = threadIdx.x;
    const int lane = tid & 31, w = tid >> 5;
    const int t = blockIdx.x * 8 + w;

    int e = 0, cnt = 0;
    if (lane == 0) {
        e   = g_last[t];
        cnt = g_cnt[t];
        g_last[t] = 0;      // reset for next replay
        g_cnt[t]  = 0;
    }
    e   = __shfl_sync(0xffffffffu, e, 0);
    cnt = __shfl_sync(0xffffffffu, cnt, 0);

    double contrib = 0.0;
    if (e > 0 && cnt > 0) {
        const int idx = e - 1;
        const int b   = idx >> 14;           // /16384
        const int r   = idx & 16383;
        const int sh  = r >> 7;              // span index within block, 0..127
        const int off = r & 127;             // element offset within span

        double acc = 0.0;
        // spans fully before the last-occurrence span
        for (int s = lane; s < sh; s += 32) acc += (double)g_wc[b * SPANS + s];

        // partial span: 128 contiguous elems, lane covers 4
        const float4* o4 = (const float4*)outs;
        float4 v = o4[b * (TILE / 4) + sh * 32 + lane];
        const int e0 = lane * 4;
        if (e0     <= off) acc += (double)__expf(v.x);
        if (e0 + 1 <= off) acc += (double)__expf(v.y);
        if (e0 + 2 <= off) acc += (double)__expf(v.z);
        if (e0 + 3 <= off) acc += (double)__expf(v.w);

#pragma unroll
        for (int o = 16; o; o >>= 1) acc += __shfl_xor_sync(0xffffffffu, acc, o);

        if (lane == 0) {
            double total = g_block_prefix[b] + acc;
            double y = log(total);
            if (y < 0.0) y = 0.0;
            contrib = y * (double)cnt;
        }
    }

    __shared__ double cs[8];
    if (lane == 0) cs[w] = contrib;
    __syncthreads();
    if (tid == 0) {
        double s = 0.0;
#pragma unroll
        for (int k = 0; k < 8; k++) s += cs[k];
        atomicAdd(&g_s2, s);
        __threadfence();
        unsigned int old = atomicAdd(&g_done, 1u);
        if (old == 127u) {
            double s2 = atomicAdd(&g_s2, 0.0);   // atomic read (L2-coherent)
            double loss = (s2 - g_s1) / (double)g_obs;
            out[0] = (float)loss;
            // reset scalars for next replay
            g_s2 = 0.0; g_s1 = 0.0; g_obs = 0ull; g_done = 0u;
        }
    }
}

// ---------------------------------------------------------------- launch
extern "C" void kernel_launch(void* const* d_in, const int* in_sizes, int n_in,
                              void* d_out, int out_size) {
    const float* outs = (const float*)d_in[0];
    const int*   T_E  = (const int*)d_in[1];
    const int*   T_T  = (const int*)d_in[2];
    float* out = (float*)d_out;

    k1_main<<<NBLK, THREADS>>>(outs, T_E, T_T);
    k2_scan<<<1, 1024>>>();
    k3_finalize<<<128, THREADS>>>(outs, out);
}